// round 6
// baseline (speedup 1.0000x reference)
#include <cuda_runtime.h>

#define P      16384
#define BM     128
#define NC     10
#define KSEL   819
#define NMASK  9830
#define NT     512
#define EQCAP  1024

// scratch (no allocations allowed)
__device__ unsigned char g_block[BM * P];
__device__ int g_cidx[BM * NC];

// monotone uint transform for float ordering (handles tiny negative d2)
__device__ __forceinline__ unsigned int fkey(float f) {
    unsigned int u = __float_as_uint(f);
    return u ^ ((u >> 31) ? 0xFFFFFFFFu : 0x80000000u);
}

struct SelResult { unsigned int T; int ties; };

// Find the key value of rank r (1-based) among keys[0..n).
// Returns threshold key T and ties = rank within the ==T group, so the selected
// set is {key < T} plus the `ties` smallest-index elements with key == T.
__device__ SelResult radix_select(const unsigned int* keys, int n, int r,
                                  int* hist, int* s_sb, int* s_cum) {
    int t = threadIdx.x;
    unsigned int prefix = 0, pmask = 0;
    int remaining = r;
    for (int shift = 24; shift >= 0; shift -= 8) {
        for (int i = t; i < 256; i += NT) hist[i] = 0;
        __syncthreads();
        for (int p = t; p < n; p += NT) {
            unsigned int k = keys[p];
            if ((k & pmask) == prefix) {
                unsigned int bkt = (k >> shift) & 255u;
                unsigned int m = __match_any_sync(__activemask(), bkt);
                int leader = __ffs(m) - 1;
                if ((int)(threadIdx.x & 31) == leader)
                    atomicAdd(&hist[bkt], __popc(m));
            }
        }
        __syncthreads();
        if (t == 0) {
            int cum = 0, sb = 255;
            for (int bkt = 0; bkt < 256; bkt++) {
                int h = hist[bkt];
                if (cum + h >= remaining) { sb = bkt; break; }
                cum += h;
            }
            *s_sb = sb; *s_cum = cum;
        }
        __syncthreads();
        prefix |= ((unsigned int)(*s_sb)) << shift;
        pmask  |= 0xFFu << shift;
        remaining -= *s_cum;
        __syncthreads();
    }
    SelResult res; res.T = prefix; res.ties = remaining;
    return res;
}

// Kernel 1: per mask-row, zero block scratch + pick 10 smallest rand_centers
// via unique u64 keys (value<<32 | idx) -> stable-argsort tie semantics.
__global__ void k_centers(const float* __restrict__ rc) {
    int b = blockIdx.x, t = threadIdx.x;
    for (int p = t; p < P; p += NT) g_block[(size_t)b * P + p] = 0;
    __shared__ unsigned long long s_min;
    unsigned long long low = 0;
    for (int i = 0; i < NC; i++) {
        if (t == 0) s_min = ~0ull;
        __syncthreads();
        unsigned long long local = ~0ull;
        for (int p = t; p < P; p += NT) {
            unsigned long long key =
                ((unsigned long long)__float_as_uint(rc[(size_t)b * P + p]) << 32) | (unsigned int)p;
            if (key >= low && key < local) local = key;
        }
        atomicMin(&s_min, local);
        __syncthreads();
        unsigned long long m = s_min;
        if (t == 0) g_cidx[b * NC + i] = (int)(m & 0xFFFFFFFFull);
        low = m + 1;
        __syncthreads();
    }
}

// Kernel 2: one block per (row, center). Eager-JAX fp32 lowering:
//   norms: unfused (x*x+y*y)+z*z  (squares materialized, sequential reduce)
//   dot:   FMA chain ascending k (Eigen / cuBLAS fp32 accumulation)
//   d2 = (ns+nc) - rn(2*dot), unfused.
// Radix-select rank 819, mark block positions.
__global__ void k_knn(const float* __restrict__ centers) {
    extern __shared__ unsigned int s_keys[];   // P keys (64 KB)
    __shared__ int hist[256];
    __shared__ int s_sb, s_cum, s_eqcnt;
    __shared__ int s_eq[EQCAP];
    int b = blockIdx.x / NC, c = blockIdx.x % NC;
    int t = threadIdx.x;
    const float* cen = centers + (size_t)(b >> 1) * P * 3;
    int ci = g_cidx[b * NC + c];
    float sx = cen[(size_t)ci * 3 + 0];
    float sy = cen[(size_t)ci * 3 + 1];
    float sz = cen[(size_t)ci * 3 + 2];
    float ns = __fadd_rn(__fadd_rn(__fmul_rn(sx, sx), __fmul_rn(sy, sy)), __fmul_rn(sz, sz));
    for (int p = t; p < P; p += NT) {
        float x = cen[(size_t)p * 3 + 0];
        float y = cen[(size_t)p * 3 + 1];
        float z = cen[(size_t)p * 3 + 2];
        float nc2 = __fadd_rn(__fadd_rn(__fmul_rn(x, x), __fmul_rn(y, y)), __fmul_rn(z, z));
        float dot = __fmaf_rn(sz, z, __fmaf_rn(sy, y, __fmul_rn(sx, x)));
        float d2 = __fsub_rn(__fadd_rn(ns, nc2), __fmul_rn(2.0f, dot));
        s_keys[p] = fkey(d2);
    }
    if (t == 0) s_eqcnt = 0;
    __syncthreads();
    SelResult sr = radix_select(s_keys, P, KSEL, hist, &s_sb, &s_cum);
    unsigned char* brow = g_block + (size_t)b * P;
    for (int p = t; p < P; p += NT) {
        unsigned int k = s_keys[p];
        if (k < sr.T) brow[p] = 1;
        else if (k == sr.T) {
            int pos = atomicAdd(&s_eqcnt, 1);
            if (pos < EQCAP) s_eq[pos] = p;
        }
    }
    __syncthreads();
    int L = s_eqcnt;
    if (L <= EQCAP) {
        for (int i = t; i < L; i += NT) {
            int p = s_eq[i]; int rank = 0;
            for (int j = 0; j < L; j++) if (s_eq[j] < p) rank++;
            if (rank < sr.ties) brow[p] = 1;
        }
    } else {  // pathological tie explosion fallback (still exact)
        for (int p = t; p < P; p += NT) {
            if (s_keys[p] == sr.T) {
                int rank = 0;
                for (int j = 0; j < p; j++) if (s_keys[j] == sr.T) rank++;
                if (rank < sr.ties) brow[p] = 1;
            }
        }
    }
}

// Kernel 3: per row, select (9830 - n_block) smallest rand_mask among
// non-block positions (stable ties by index), write FLOAT32 mask (0.0/1.0).
__global__ void k_final(const float* __restrict__ rm, float* __restrict__ out) {
    extern __shared__ unsigned int s_keys[];   // P keys (64 KB)
    __shared__ int hist[256];
    __shared__ int s_sb, s_cum, s_eqcnt, s_nblk;
    __shared__ int s_eq[EQCAP];
    int b = blockIdx.x, t = threadIdx.x;
    if (t == 0) { s_eqcnt = 0; s_nblk = 0; }
    __syncthreads();
    const unsigned char* brow = g_block + (size_t)b * P;
    int local = 0;
    for (int p = t; p < P; p += NT) {
        unsigned char blk = brow[p];
        local += blk;
        s_keys[p] = blk ? 0xFFFFFFFFu : __float_as_uint(rm[(size_t)b * P + p]);
    }
    atomicAdd(&s_nblk, local);
    __syncthreads();
    int k = NMASK - s_nblk;   // >= 1640 always (n_block <= 8190)
    SelResult sr = radix_select(s_keys, P, k, hist, &s_sb, &s_cum);
    float* orow = out + (size_t)b * P;
    for (int p = t; p < P; p += NT) {
        unsigned int kk = s_keys[p];
        float v = (kk == 0xFFFFFFFFu) ? 1.0f : (kk < sr.T ? 1.0f : 0.0f);
        orow[p] = v;
        if (kk == sr.T) {
            int pos = atomicAdd(&s_eqcnt, 1);
            if (pos < EQCAP) s_eq[pos] = p;
        }
    }
    __syncthreads();
    int L = s_eqcnt;
    if (L <= EQCAP) {
        for (int i = t; i < L; i += NT) {
            int p = s_eq[i]; int rank = 0;
            for (int j = 0; j < L; j++) if (s_eq[j] < p) rank++;
            if (rank < sr.ties) orow[p] = 1.0f;
        }
    } else {
        for (int p = t; p < P; p += NT) {
            if (s_keys[p] == sr.T) {
                int rank = 0;
                for (int j = 0; j < p; j++) if (s_keys[j] == sr.T) rank++;
                if (rank < sr.ties) orow[p] = 1.0f;
            }
        }
    }
}

extern "C" void kernel_launch(void* const* d_in, const int* in_sizes, int n_in,
                              void* d_out, int out_size) {
    const float* centers = (const float*)d_in[0];  // [64, 16384, 3]
    const float* rc      = (const float*)d_in[1];  // [128, 16384]
    const float* rm      = (const float*)d_in[2];  // [128, 16384]
    float* out           = (float*)d_out;          // [128, 16384] float32 (bool->f32)

    cudaFuncSetAttribute(k_knn,   cudaFuncAttributeMaxDynamicSharedMemorySize, P * 4);
    cudaFuncSetAttribute(k_final, cudaFuncAttributeMaxDynamicSharedMemorySize, P * 4);

    k_centers<<<BM, NT>>>(rc);
    k_knn<<<BM * NC, NT, P * 4>>>(centers);
    k_final<<<BM, NT, P * 4>>>(rm, out);
}